// round 5
// baseline (speedup 1.0000x reference)
#include <cuda_runtime.h>
#include <cstdint>

#define N_IMG 32
#define C_IN  128
#define H_DIM 56
#define W_DIM 56
#define P_OUT 128
#define HPAD  (H_DIM + 2)     // 58
#define BN_EPS 1e-5f
#define PSTR  144             // smem pixel stride (bytes): 36 banks -> conflict-free frags

// Scratch (__device__ globals per allocation-free rule)
__device__ __align__(16) char  g_as8[(size_t)N_IMG * HPAD * HPAD * C_IN]; // 13.8 MB, NHWC s8, zero border
__device__ uint4  g_wfrag[9 * 4 * 8 * 32];   // weights in mma A-fragment order, 18.4 KB
__device__ float2 g_sc[P_OUT];               // (scale, offset) fused bias+BN

// ---------------------------------------------------------------------------
// Pack weights directly into m16n8k32 A-fragment layout:
//   frag index = ((tap*4 + kc)*8 + mtile)*32 + lane, payload = 4 regs:
//   reg rr: row p = mtile*16 + lane/4 + (rr&1)*8, chans cb = kc*32 + (lane%3..)*4 + (rr>>1)*16
// ---------------------------------------------------------------------------
__global__ void pack_w_kernel(const float* __restrict__ w,
                              const float* __restrict__ bias,
                              const float* __restrict__ gamma,
                              const float* __restrict__ beta,
                              const float* __restrict__ rmean,
                              const float* __restrict__ rvar) {
    int idx = blockIdx.x * 256 + threadIdx.x;     // 0..9215
    if (idx < 9 * 1024) {
        int lane = idx & 31;
        int mt   = (idx >> 5) & 7;
        int kc   = (idx >> 8) & 3;
        int tap  = idx >> 10;                     // 0..8
        unsigned r[4];
        #pragma unroll
        for (int rr = 0; rr < 4; rr++) {
            int p  = mt * 16 + (lane >> 2) + (rr & 1) * 8;
            int cb = kc * 32 + (lane & 3) * 4 + (rr >> 1) * 16;
            unsigned v = 0;
            #pragma unroll
            for (int j = 0; j < 4; j++) {
                float wv = w[(size_t)(p * C_IN + cb + j) * 9 + tap];
                v |= (wv >= 0.0f ? 0x01u : 0xFFu) << (8 * j);
            }
            r[rr] = v;
        }
        g_wfrag[idx] = make_uint4(r[0], r[1], r[2], r[3]);
    }
    if (blockIdx.x == 0 && threadIdx.x < P_OUT) {
        int p = threadIdx.x;
        float inv = gamma[p] / sqrtf(rvar[p] + BN_EPS);
        g_sc[p] = make_float2(inv, bias[p] * inv + beta[p] - rmean[p] * inv);
    }
}

// ---------------------------------------------------------------------------
// Pack activations: NCHW f32 -> NHWC s8 (+1/-1), 1-pixel ZERO border
// (int8 zero contributes 0 to the dot product -> exact conv padding).
// ---------------------------------------------------------------------------
__global__ void __launch_bounds__(256) pack_a_kernel(const float* __restrict__ x) {
    int b  = blockIdx.x;                 // n * 15 + row-quad
    int rq = b % 15, n = b / 15;
    int hp = rq * 4 + (threadIdx.x >> 6);
    int wp = threadIdx.x & 63;
    if (hp >= HPAD || wp >= HPAD) return;

    uint4* dst = (uint4*)(g_as8 + ((size_t)(n * HPAD + hp) * HPAD + wp) * C_IN);
    if (hp == 0 || hp == HPAD - 1 || wp == 0 || wp == HPAD - 1) {
        uint4 z = make_uint4(0u, 0u, 0u, 0u);
        #pragma unroll
        for (int i = 0; i < 8; i++) dst[i] = z;
    } else {
        const float* base = x + (size_t)n * C_IN * H_DIM * W_DIM
                              + (hp - 1) * W_DIM + (wp - 1);
        unsigned words[32];
        #pragma unroll
        for (int u = 0; u < 32; u++) {
            unsigned v = 0;
            #pragma unroll
            for (int j = 0; j < 4; j++) {
                float f = base[(size_t)(u * 4 + j) * H_DIM * W_DIM];
                v |= (f >= 0.0f ? 0x01u : 0xFFu) << (8 * j);
            }
            words[u] = v;
        }
        #pragma unroll
        for (int i = 0; i < 8; i++)
            dst[i] = make_uint4(words[i*4], words[i*4+1], words[i*4+2], words[i*4+3]);
    }
}

// ---------------------------------------------------------------------------
// Implicit-GEMM binary conv on the tensor pipe (IMMA m16n8k32 s8).
// Block: 256 thr = 8 warps (warp = 16-channel M-tile), 2 output rows x 56 px.
// K loop = 9 taps x 4 chan-chunks; B-frags from smem (conflict-free, bank=lane),
// A-frags one LDG.128 from the fragment-ordered weight buffer (L1/L2 hot).
// Epilogue fuses bias+BN scale/offset and the fp32 residual add.
// ---------------------------------------------------------------------------
__device__ __forceinline__ void mma_s8(int* d, uint4 a, unsigned b0, unsigned b1) {
    asm volatile(
        "mma.sync.aligned.m16n8k32.row.col.s32.s8.s8.s32 "
        "{%0,%1,%2,%3}, {%4,%5,%6,%7}, {%8,%9}, {%0,%1,%2,%3};"
        : "+r"(d[0]), "+r"(d[1]), "+r"(d[2]), "+r"(d[3])
        : "r"(a.x), "r"(a.y), "r"(a.z), "r"(a.w), "r"(b0), "r"(b1));
}

__global__ void __launch_bounds__(256)
conv_kernel(const float* __restrict__ x, float* __restrict__ out) {
    __shared__ __align__(16) char s_act[4 * HPAD * PSTR];   // 33.4 KB
    __shared__ float2 s_sc[P_OUT];

    int b = blockIdx.x;
    int n = b / (H_DIM / 2), h0 = (b % (H_DIM / 2)) * 2;
    int t = threadIdx.x;

    // stage 4 padded activation rows (h0 .. h0+3 in padded space)
    if (t < 4 * HPAD) {
        int rr = t / HPAD, wp = t % HPAD;
        const uint4* src = (const uint4*)(g_as8 +
            ((size_t)(n * HPAD + h0 + rr) * HPAD + wp) * C_IN);
        uint4* dst = (uint4*)(s_act + (rr * HPAD + wp) * PSTR);
        #pragma unroll
        for (int i = 0; i < 8; i++) dst[i] = src[i];
    }
    if (t < P_OUT) s_sc[t] = g_sc[t];
    __syncthreads();

    int wid = t >> 5, lane = t & 31;
    int qid = lane >> 2, tid4 = lane & 3;

    int D[14][4];
    #pragma unroll
    for (int g = 0; g < 14; g++) {
        D[g][0] = 0; D[g][1] = 0; D[g][2] = 0; D[g][3] = 0;
    }

    // per-group smem byte offsets: pixel (row g/7, col (g%7)*8 + qid), chan byte (tid4)*4
    int gaddr[14];
    #pragma unroll
    for (int g = 0; g < 14; g++)
        gaddr[g] = ((g / 7) * HPAD + (g % 7) * 8 + qid) * PSTR + tid4 * 4;

    for (int tap = 0; tap < 9; tap++) {
        int toff = ((tap / 3) * HPAD + (tap % 3)) * PSTR;
        #pragma unroll
        for (int kc = 0; kc < 4; kc++) {
            uint4 A = g_wfrag[((tap * 4 + kc) * 8 + wid) * 32 + lane];
            int koff = toff + kc * 32;
            #pragma unroll
            for (int g = 0; g < 14; g++) {
                unsigned b0 = *(const unsigned*)(s_act + gaddr[g] + koff);
                unsigned b1 = *(const unsigned*)(s_act + gaddr[g] + koff + 16);
                mma_s8(D[g], A, b0, b1);
            }
        }
    }

    // epilogue: D rows p0 = wid*16+qid and p1 = p0+8; cols w = (g%7)*8 + tid4*2 (+1)
    float2 sc0 = s_sc[wid * 16 + qid];
    float2 sc1 = s_sc[wid * 16 + qid + 8];
    size_t base0 = ((size_t)(n * P_OUT + wid * 16 + qid) * H_DIM + h0) * W_DIM + tid4 * 2;
    size_t base1 = base0 + (size_t)8 * H_DIM * W_DIM;

    #pragma unroll
    for (int g = 0; g < 14; g++) {
        int off = (g / 7) * W_DIM + (g % 7) * 8;
        float2 x0 = *(const float2*)(x + base0 + off);
        float2 x1 = *(const float2*)(x + base1 + off);
        float2 o0, o1;
        o0.x = (float)D[g][0] * sc0.x + sc0.y + x0.x;
        o0.y = (float)D[g][1] * sc0.x + sc0.y + x0.y;
        o1.x = (float)D[g][2] * sc1.x + sc1.y + x1.x;
        o1.y = (float)D[g][3] * sc1.x + sc1.y + x1.y;
        *(float2*)(out + base0 + off) = o0;
        *(float2*)(out + base1 + off) = o1;
    }
}

// ---------------------------------------------------------------------------
extern "C" void kernel_launch(void* const* d_in, const int* in_sizes, int n_in,
                              void* d_out, int out_size) {
    const float* x     = (const float*)d_in[0];
    const float* w     = (const float*)d_in[1];
    const float* bias  = (const float*)d_in[2];
    const float* gamma = (const float*)d_in[3];
    const float* beta  = (const float*)d_in[4];
    const float* rmean = (const float*)d_in[5];
    const float* rvar  = (const float*)d_in[6];
    float* out = (float*)d_out;

    pack_w_kernel<<<36, 256>>>(w, bias, gamma, beta, rmean, rvar);
    pack_a_kernel<<<N_IMG * 15, 256>>>(x);
    conv_kernel<<<N_IMG * (H_DIM / 2), 256>>>(x, out);
}

// round 6
// speedup vs baseline: 1.0003x; 1.0003x over previous
#include <cuda_runtime.h>
#include <cstdint>

#define N_IMG 32
#define C_IN  128
#define H_DIM 56
#define W_DIM 56
#define P_OUT 128
#define HPAD  (H_DIM + 2)     // 58
#define BN_EPS 1e-5f
#define PSTR  144             // smem pixel stride (bytes): 36 banks -> conflict-free frags

// Scratch (__device__ globals per allocation-free rule)
__device__ __align__(16) char  g_as8[(size_t)N_IMG * HPAD * HPAD * C_IN]; // 13.8 MB, NHWC s8, zero border
__device__ uint4  g_wfrag[9 * 4 * 8 * 32];   // weights in mma A-fragment order, 18.4 KB
__device__ float2 g_sc[P_OUT];               // (scale, offset) fused bias+BN

// ---------------------------------------------------------------------------
// Pack weights directly into m16n8k32 A-fragment layout:
//   frag index = ((tap*4 + kc)*8 + mtile)*32 + lane, payload = 4 regs:
//   reg rr: row p = mtile*16 + lane/4 + (rr&1)*8, chans cb = kc*32 + (lane%3..)*4 + (rr>>1)*16
// ---------------------------------------------------------------------------
__global__ void pack_w_kernel(const float* __restrict__ w,
                              const float* __restrict__ bias,
                              const float* __restrict__ gamma,
                              const float* __restrict__ beta,
                              const float* __restrict__ rmean,
                              const float* __restrict__ rvar) {
    int idx = blockIdx.x * 256 + threadIdx.x;     // 0..9215
    if (idx < 9 * 1024) {
        int lane = idx & 31;
        int mt   = (idx >> 5) & 7;
        int kc   = (idx >> 8) & 3;
        int tap  = idx >> 10;                     // 0..8
        unsigned r[4];
        #pragma unroll
        for (int rr = 0; rr < 4; rr++) {
            int p  = mt * 16 + (lane >> 2) + (rr & 1) * 8;
            int cb = kc * 32 + (lane & 3) * 4 + (rr >> 1) * 16;
            unsigned v = 0;
            #pragma unroll
            for (int j = 0; j < 4; j++) {
                float wv = w[(size_t)(p * C_IN + cb + j) * 9 + tap];
                v |= (wv >= 0.0f ? 0x01u : 0xFFu) << (8 * j);
            }
            r[rr] = v;
        }
        g_wfrag[idx] = make_uint4(r[0], r[1], r[2], r[3]);
    }
    if (blockIdx.x == 0 && threadIdx.x < P_OUT) {
        int p = threadIdx.x;
        float inv = gamma[p] / sqrtf(rvar[p] + BN_EPS);
        g_sc[p] = make_float2(inv, bias[p] * inv + beta[p] - rmean[p] * inv);
    }
}

// ---------------------------------------------------------------------------
// Pack activations: NCHW f32 -> NHWC s8 (+1/-1), 1-pixel ZERO border
// (int8 zero contributes 0 to the dot product -> exact conv padding).
// ---------------------------------------------------------------------------
__global__ void __launch_bounds__(256) pack_a_kernel(const float* __restrict__ x) {
    int b  = blockIdx.x;                 // n * 15 + row-quad
    int rq = b % 15, n = b / 15;
    int hp = rq * 4 + (threadIdx.x >> 6);
    int wp = threadIdx.x & 63;
    if (hp >= HPAD || wp >= HPAD) return;

    uint4* dst = (uint4*)(g_as8 + ((size_t)(n * HPAD + hp) * HPAD + wp) * C_IN);
    if (hp == 0 || hp == HPAD - 1 || wp == 0 || wp == HPAD - 1) {
        uint4 z = make_uint4(0u, 0u, 0u, 0u);
        #pragma unroll
        for (int i = 0; i < 8; i++) dst[i] = z;
    } else {
        const float* base = x + (size_t)n * C_IN * H_DIM * W_DIM
                              + (hp - 1) * W_DIM + (wp - 1);
        unsigned words[32];
        #pragma unroll
        for (int u = 0; u < 32; u++) {
            unsigned v = 0;
            #pragma unroll
            for (int j = 0; j < 4; j++) {
                float f = base[(size_t)(u * 4 + j) * H_DIM * W_DIM];
                v |= (f >= 0.0f ? 0x01u : 0xFFu) << (8 * j);
            }
            words[u] = v;
        }
        #pragma unroll
        for (int i = 0; i < 8; i++)
            dst[i] = make_uint4(words[i*4], words[i*4+1], words[i*4+2], words[i*4+3]);
    }
}

// ---------------------------------------------------------------------------
// Implicit-GEMM binary conv on the tensor pipe (IMMA m16n8k32 s8).
// Block: 256 thr = 8 warps (warp = 16-channel M-tile), 2 output rows x 56 px.
// K loop = 9 taps x 4 chan-chunks; B-frags from smem (conflict-free, bank=lane),
// A-frags one LDG.128 from the fragment-ordered weight buffer (L1/L2 hot).
// Epilogue fuses bias+BN scale/offset and the fp32 residual add.
// ---------------------------------------------------------------------------
__device__ __forceinline__ void mma_s8(int* d, uint4 a, unsigned b0, unsigned b1) {
    asm volatile(
        "mma.sync.aligned.m16n8k32.row.col.s32.s8.s8.s32 "
        "{%0,%1,%2,%3}, {%4,%5,%6,%7}, {%8,%9}, {%0,%1,%2,%3};"
        : "+r"(d[0]), "+r"(d[1]), "+r"(d[2]), "+r"(d[3])
        : "r"(a.x), "r"(a.y), "r"(a.z), "r"(a.w), "r"(b0), "r"(b1));
}

__global__ void __launch_bounds__(256)
conv_kernel(const float* __restrict__ x, float* __restrict__ out) {
    __shared__ __align__(16) char s_act[4 * HPAD * PSTR];   // 33.4 KB
    __shared__ float2 s_sc[P_OUT];

    int b = blockIdx.x;
    int n = b / (H_DIM / 2), h0 = (b % (H_DIM / 2)) * 2;
    int t = threadIdx.x;

    // stage 4 padded activation rows (h0 .. h0+3 in padded space)
    if (t < 4 * HPAD) {
        int rr = t / HPAD, wp = t % HPAD;
        const uint4* src = (const uint4*)(g_as8 +
            ((size_t)(n * HPAD + h0 + rr) * HPAD + wp) * C_IN);
        uint4* dst = (uint4*)(s_act + (rr * HPAD + wp) * PSTR);
        #pragma unroll
        for (int i = 0; i < 8; i++) dst[i] = src[i];
    }
    if (t < P_OUT) s_sc[t] = g_sc[t];
    __syncthreads();

    int wid = t >> 5, lane = t & 31;
    int qid = lane >> 2, tid4 = lane & 3;

    int D[14][4];
    #pragma unroll
    for (int g = 0; g < 14; g++) {
        D[g][0] = 0; D[g][1] = 0; D[g][2] = 0; D[g][3] = 0;
    }

    // per-group smem byte offsets: pixel (row g/7, col (g%7)*8 + qid), chan byte (tid4)*4
    int gaddr[14];
    #pragma unroll
    for (int g = 0; g < 14; g++)
        gaddr[g] = ((g / 7) * HPAD + (g % 7) * 8 + qid) * PSTR + tid4 * 4;

    for (int tap = 0; tap < 9; tap++) {
        int toff = ((tap / 3) * HPAD + (tap % 3)) * PSTR;
        #pragma unroll
        for (int kc = 0; kc < 4; kc++) {
            uint4 A = g_wfrag[((tap * 4 + kc) * 8 + wid) * 32 + lane];
            int koff = toff + kc * 32;
            #pragma unroll
            for (int g = 0; g < 14; g++) {
                unsigned b0 = *(const unsigned*)(s_act + gaddr[g] + koff);
                unsigned b1 = *(const unsigned*)(s_act + gaddr[g] + koff + 16);
                mma_s8(D[g], A, b0, b1);
            }
        }
    }

    // epilogue: D rows p0 = wid*16+qid and p1 = p0+8; cols w = (g%7)*8 + tid4*2 (+1)
    float2 sc0 = s_sc[wid * 16 + qid];
    float2 sc1 = s_sc[wid * 16 + qid + 8];
    size_t base0 = ((size_t)(n * P_OUT + wid * 16 + qid) * H_DIM + h0) * W_DIM + tid4 * 2;
    size_t base1 = base0 + (size_t)8 * H_DIM * W_DIM;

    #pragma unroll
    for (int g = 0; g < 14; g++) {
        int off = (g / 7) * W_DIM + (g % 7) * 8;
        float2 x0 = *(const float2*)(x + base0 + off);
        float2 x1 = *(const float2*)(x + base1 + off);
        float2 o0, o1;
        o0.x = (float)D[g][0] * sc0.x + sc0.y + x0.x;
        o0.y = (float)D[g][1] * sc0.x + sc0.y + x0.y;
        o1.x = (float)D[g][2] * sc1.x + sc1.y + x1.x;
        o1.y = (float)D[g][3] * sc1.x + sc1.y + x1.y;
        *(float2*)(out + base0 + off) = o0;
        *(float2*)(out + base1 + off) = o1;
    }
}

// ---------------------------------------------------------------------------
extern "C" void kernel_launch(void* const* d_in, const int* in_sizes, int n_in,
                              void* d_out, int out_size) {
    const float* x     = (const float*)d_in[0];
    const float* w     = (const float*)d_in[1];
    const float* bias  = (const float*)d_in[2];
    const float* gamma = (const float*)d_in[3];
    const float* beta  = (const float*)d_in[4];
    const float* rmean = (const float*)d_in[5];
    const float* rvar  = (const float*)d_in[6];
    float* out = (float*)d_out;

    pack_w_kernel<<<36, 256>>>(w, bias, gamma, beta, rmean, rvar);
    pack_a_kernel<<<N_IMG * 15, 256>>>(x);
    conv_kernel<<<N_IMG * (H_DIM / 2), 256>>>(x, out);
}

// round 8
// speedup vs baseline: 1.6207x; 1.6203x over previous
#include <cuda_runtime.h>
#include <cstdint>

#define N_IMG 32
#define C_IN  128
#define H_DIM 56
#define W_DIM 56
#define P_OUT 128
#define HP (H_DIM + 2)
#define WP (W_DIM + 2)
#define BN_EPS 1e-5f

// Scratch (allocation-free rule: __device__ globals)
__device__ uint4  g_apack[N_IMG * HP * WP];   // packed activations, zero border
__device__ uint4  g_wpack[P_OUT * 9];         // packed weights per tap (4 x u32)
__device__ int    g_corr[P_OUT * 8];          // border-correction values per out-channel
__device__ float2 g_sc[P_OUT];                // (scale, offset) fused bias+BN

// full adder: 3 bit-vectors -> sum (same weight) + carry (double weight). 2 LOP3.
__device__ __forceinline__ void fa(unsigned a, unsigned b, unsigned c,
                                   unsigned &s, unsigned &cy) {
    s  = a ^ b ^ c;
    cy = (a & b) | (a & c) | (b & c);
}

// Harley-Seal: popcount-sum of 36 words with 34 adders (68 LOP3) + 6 POPC.
__device__ __forceinline__ int popc36(const unsigned* t) {
    unsigned c2[18]; int n2 = 0;
    unsigned s1[12];
    #pragma unroll
    for (int i = 0; i < 12; i++) {
        unsigned s, c; fa(t[3*i], t[3*i+1], t[3*i+2], s, c);
        s1[i] = s; c2[n2++] = c;
    }
    unsigned s1b[4];
    #pragma unroll
    for (int i = 0; i < 4; i++) {
        unsigned s, c; fa(s1[3*i], s1[3*i+1], s1[3*i+2], s, c);
        s1b[i] = s; c2[n2++] = c;
    }
    unsigned u1, u2; fa(s1b[0], s1b[1], s1b[2], u1, u2);
    c2[n2++] = u2;
    unsigned v1 = u1 ^ s1b[3];
    c2[n2++] = u1 & s1b[3];                       // n2 == 18

    unsigned c4[9]; int n4 = 0;
    unsigned s2[6];
    #pragma unroll
    for (int i = 0; i < 6; i++) {
        unsigned s, c; fa(c2[3*i], c2[3*i+1], c2[3*i+2], s, c);
        s2[i] = s; c4[n4++] = c;
    }
    unsigned s2b[2];
    #pragma unroll
    for (int i = 0; i < 2; i++) {
        unsigned s, c; fa(s2[3*i], s2[3*i+1], s2[3*i+2], s, c);
        s2b[i] = s; c4[n4++] = c;
    }
    unsigned v2 = s2b[0] ^ s2b[1];
    c4[n4++] = s2b[0] & s2b[1];                   // n4 == 9

    unsigned c8[4]; int n8 = 0;
    unsigned s4[3];
    #pragma unroll
    for (int i = 0; i < 3; i++) {
        unsigned s, c; fa(c4[3*i], c4[3*i+1], c4[3*i+2], s, c);
        s4[i] = s; c8[n8++] = c;
    }
    unsigned v4, c8b; fa(s4[0], s4[1], s4[2], v4, c8b);
    c8[n8++] = c8b;                               // n8 == 4

    unsigned s8, c16a; fa(c8[0], c8[1], c8[2], s8, c16a);
    unsigned v8   = s8 ^ c8[3];
    unsigned c16b = s8 & c8[3];
    unsigned v16  = c16a ^ c16b;
    unsigned v32  = c16a & c16b;

    return __popc(v1) + 2 * __popc(v2) + 4 * __popc(v4)
         + 8 * __popc(v8) + 16 * __popc(v16) + 32 * __popc(v32);
}

// ---------------------------------------------------------------------------
// Pack weights (parallel): one block per output channel, ballot-based packing.
// ---------------------------------------------------------------------------
__global__ void pack_w_kernel(const float* __restrict__ w,
                              const float* __restrict__ bias,
                              const float* __restrict__ gamma,
                              const float* __restrict__ beta,
                              const float* __restrict__ rmean,
                              const float* __restrict__ rvar) {
    int p = blockIdx.x;           // 0..127
    int c = threadIdx.x;          // 0..127 (input channel)
    int lane = c & 31, wd = c >> 5;

    __shared__ unsigned sw[9][4];
    __shared__ int ssum[9];

    #pragma unroll
    for (int t = 0; t < 9; t++) {
        float v = w[(size_t)(p * C_IN + c) * 9 + t];
        unsigned m = __ballot_sync(0xffffffffu, v >= 0.0f);
        if (lane == 0) sw[t][wd] = m;
    }
    __syncthreads();

    if (c < 9) {
        int t = c;
        int pc = __popc(sw[t][0]) + __popc(sw[t][1]) + __popc(sw[t][2]) + __popc(sw[t][3]);
        ssum[t] = 2 * pc - C_IN;
    }
    __syncthreads();

    if (c < 9) {
        g_wpack[p * 9 + c] = make_uint4(sw[c][0], sw[c][1], sw[c][2], sw[c][3]);
    }
    if (c == 0) {
        const int* ws = ssum;
        g_corr[p * 8 + 0] = ws[0] + ws[1] + ws[2];   // top row
        g_corr[p * 8 + 1] = ws[6] + ws[7] + ws[8];   // bottom row
        g_corr[p * 8 + 2] = ws[0] + ws[3] + ws[6];   // left col
        g_corr[p * 8 + 3] = ws[2] + ws[5] + ws[8];   // right col
        g_corr[p * 8 + 4] = ws[0];                   // corners
        g_corr[p * 8 + 5] = ws[2];
        g_corr[p * 8 + 6] = ws[6];
        g_corr[p * 8 + 7] = ws[8];

        float inv = gamma[p] / sqrtf(rvar[p] + BN_EPS);
        float offs = bias[p] * inv + beta[p] - rmean[p] * inv;
        g_sc[p] = make_float2(inv, offs);
    }
}

// ---------------------------------------------------------------------------
// Pack activations with 1-pixel zero border. 256 threads cover 4 padded rows.
// ---------------------------------------------------------------------------
__global__ void __launch_bounds__(256) pack_a_kernel(const float* __restrict__ x) {
    int b = blockIdx.x;                 // (n, row-quad)
    int rq = b % ((HP + 3) / 4);
    int n  = b / ((HP + 3) / 4);
    int hp = rq * 4 + (threadIdx.x >> 6);
    int wp = threadIdx.x & 63;
    if (hp >= HP || wp >= WP) return;

    uint4 out = make_uint4(0u, 0u, 0u, 0u);
    if (hp >= 1 && hp <= H_DIM && wp >= 1 && wp <= W_DIM) {
        int h = hp - 1, w = wp - 1;
        const float* base = x + (size_t)n * C_IN * H_DIM * W_DIM + h * W_DIM + w;
        unsigned int words[4] = {0u, 0u, 0u, 0u};
        #pragma unroll 8
        for (int c = 0; c < C_IN; c++) {
            float v = base[(size_t)c * H_DIM * W_DIM];
            words[c >> 5] |= (unsigned int)(v >= 0.0f) << (c & 31);
        }
        out = make_uint4(words[0], words[1], words[2], words[3]);
    }
    g_apack[(n * HP + hp) * WP + wp] = out;
}

// ---------------------------------------------------------------------------
// Fused XNOR conv + bias + BN + residual.
// Harley-Seal CSA over all 36 tap-words (68 LOP3 + 6 POPC per output instead
// of 40 LOP3 + 16 POPC) -- POPC is quarter-rate, LOP3 full-rate on sm_103a.
// Warp-uniform weight LDS (w = t&63, cg = t>>6); 2 output rows per thread.
// ---------------------------------------------------------------------------
__global__ void __launch_bounds__(256)
conv_kernel(const float* __restrict__ x, float* __restrict__ out) {
    __shared__ uint4  s_act[4 * WP];       // 3.7 KB
    __shared__ uint4  s_w[P_OUT * 9];      // 18 KB
    __shared__ int    s_corr[P_OUT * 8];   // 4 KB
    __shared__ float2 s_sc[P_OUT];         // 1 KB

    int b = blockIdx.x;
    int n = b / (H_DIM / 2);
    int h0 = (b % (H_DIM / 2)) * 2;        // first of two output rows
    int t = threadIdx.x;

    for (int i = t; i < P_OUT * 9; i += 256) s_w[i] = g_wpack[i];
    for (int i = t; i < P_OUT * 8; i += 256) s_corr[i] = g_corr[i];
    for (int i = t; i < P_OUT;     i += 256) s_sc[i] = g_sc[i];
    for (int i = t; i < 4 * WP;    i += 256)
        s_act[i] = g_apack[(n * HP + h0 + i / WP) * WP + (i % WP)];
    __syncthreads();

    int w = t & 63;
    int cg = t >> 6;
    if (w >= W_DIM) return;

    // 4 rows x 3 cols of packed activations in registers: xa[row][col*4+u]
    unsigned xa[4][12];
    #pragma unroll
    for (int dr = 0; dr < 4; dr++) {
        #pragma unroll
        for (int dc = 0; dc < 3; dc++) {
            uint4 v = s_act[dr * WP + w + dc];
            xa[dr][dc * 4 + 0] = v.x; xa[dr][dc * 4 + 1] = v.y;
            xa[dr][dc * 4 + 2] = v.z; xa[dr][dc * 4 + 3] = v.w;
        }
    }

    int ft0 = (h0 == 0);              // row h0 may be top
    int fb1 = (h0 + 1 == H_DIM - 1);  // row h0+1 may be bottom
    int fl = (w == 0), fr = (w == W_DIM - 1);

    const size_t cstride = (size_t)H_DIM * W_DIM;
    const float* xin0 = x   + ((size_t)(n * P_OUT + cg * 32) * H_DIM + h0) * W_DIM + w;
    float*       ob0  = out + ((size_t)(n * P_OUT + cg * 32) * H_DIM + h0) * W_DIM + w;

    for (int i = 0; i < 32; i++) {
        int p = cg * 32 + i;

        // 9 weight vectors (warp-uniform -> broadcast LDS.128)
        unsigned wv[9][4];
        #pragma unroll
        for (int tp = 0; tp < 9; tp++) {
            uint4 v = s_w[p * 9 + tp];
            wv[tp][0] = v.x; wv[tp][1] = v.y; wv[tp][2] = v.z; wv[tp][3] = v.w;
        }

        // row h0
        unsigned ta[36];
        #pragma unroll
        for (int tp = 0; tp < 9; tp++) {
            int dr = tp / 3, dc = tp % 3;
            #pragma unroll
            for (int u = 0; u < 4; u++)
                ta[tp * 4 + u] = xa[dr][dc * 4 + u] ^ wv[tp][u];
        }
        int pc0 = popc36(ta);

        // row h0+1
        unsigned tb[36];
        #pragma unroll
        for (int tp = 0; tp < 9; tp++) {
            int dr = tp / 3, dc = tp % 3;
            #pragma unroll
            for (int u = 0; u < 4; u++)
                tb[tp * 4 + u] = xa[dr + 1][dc * 4 + u] ^ wv[tp][u];
        }
        int pc1 = popc36(tb);

        int dot0 = 9 * C_IN - 2 * pc0;
        int dot1 = 9 * C_IN - 2 * pc1;

        const int* cr = &s_corr[p * 8];
        dot0 += ft0 * cr[0] + fl * cr[2] + fr * cr[3]
              - (ft0 & fl) * cr[4] - (ft0 & fr) * cr[5];
        dot1 += fb1 * cr[1] + fl * cr[2] + fr * cr[3]
              - (fb1 & fl) * cr[6] - (fb1 & fr) * cr[7];

        float2 sc = s_sc[p];
        ob0[i * cstride]         = (float)dot0 * sc.x + sc.y + xin0[i * cstride];
        ob0[i * cstride + W_DIM] = (float)dot1 * sc.x + sc.y + xin0[i * cstride + W_DIM];
    }
}

// ---------------------------------------------------------------------------
extern "C" void kernel_launch(void* const* d_in, const int* in_sizes, int n_in,
                              void* d_out, int out_size) {
    const float* x     = (const float*)d_in[0];
    const float* w     = (const float*)d_in[1];
    const float* bias  = (const float*)d_in[2];
    const float* gamma = (const float*)d_in[3];
    const float* beta  = (const float*)d_in[4];
    const float* rmean = (const float*)d_in[5];
    const float* rvar  = (const float*)d_in[6];
    float* out = (float*)d_out;

    pack_w_kernel<<<P_OUT, 128>>>(w, bias, gamma, beta, rmean, rvar);
    pack_a_kernel<<<N_IMG * ((HP + 3) / 4), 256>>>(x);
    conv_kernel<<<N_IMG * (H_DIM / 2), 256>>>(x, out);
}